// round 6
// baseline (speedup 1.0000x reference)
#include <cuda_runtime.h>
#include <math.h>

#define N_NODES 50000
#define N_EDGES 800000
#define NF 256
#define NH 64
#define NC 16
#define KD 192      // 3*NH
#define KD1 768     // 3*NF
#define N_OCT (N_NODES / 8)   // 6250

// ---------------- scratch (device globals) ----------------------------------
__device__ float g_XG[N_NODES * 128];  // conv1 gemm-first: interleaved [xW0|xD] pairs
__device__ float g_XR[N_NODES * NH];   // conv1: x @ R1
__device__ float g_h [N_NODES * NH];
__device__ float g_y [N_NODES * NH];
__device__ float g_t [N_NODES * NH];
__device__ float g_k1[N_NODES * NH];
__device__ float g_k2[N_NODES * NH];
__device__ float g_k3[N_NODES * NH];
__device__ float g_Wcat1[KD1 * NH];   // conv1 [768,64]: rows 0-255 W0, 256-511 D, 512-767 R
__device__ float g_WtA[KD * NH];      // hidden conv A, pair-transposed
__device__ float g_WtB[KD * NH];      // hidden conv B, pair-transposed
__device__ float g_Wcat2[KD * NC];    // final conv plain [192,16]
__device__ int    g_off[N_NODES + 1];
__device__ int    g_deg[N_NODES];
__device__ int    g_cur[N_NODES];
__device__ int    g_wctr[16];         // work-steal counters (one slot per launch)
__device__ float2 g_edge[N_EDGES];    // (src-as-float-bits, p)

// ---------------- packed f32x2 helpers --------------------------------------
typedef unsigned long long u64;
__device__ __forceinline__ void ffma2(u64& d, u64 a, u64 b) {
    asm("fma.rn.f32x2 %0, %1, %2, %0;" : "+l"(d) : "l"(a), "l"(b));
}
__device__ __forceinline__ u64 pack2_dup(float x) {
    u64 r;
    unsigned int u = __float_as_uint(x);
    asm("mov.b64 %0, {%1, %1};" : "=l"(r) : "r"(u));
    return r;
}
__device__ __forceinline__ void unpack2(u64 v, float& lo, float& hi) {
    unsigned int a, b;
    asm("mov.b64 {%0, %1}, %2;" : "=r"(a), "=r"(b) : "l"(v));
    lo = __uint_as_float(a);
    hi = __uint_as_float(b);
}

// ---------------- CSR build --------------------------------------------------
__global__ void k_zero() {
    int i = blockIdx.x * blockDim.x + threadIdx.x;
    if (i < N_NODES) { g_deg[i] = 0; g_cur[i] = 0; }
    if (i < 16) g_wctr[i] = 0;
}
__global__ void k_hist(const int* __restrict__ dst) {
    int e = blockIdx.x * blockDim.x + threadIdx.x;
    if (e < N_EDGES) atomicAdd(&g_deg[dst[e]], 1);
}
__global__ void k_scan() {
    __shared__ int sm[1024];
    int t = threadIdx.x;
    const int CH = (N_NODES + 1023) / 1024;
    int base = t * CH;
    int s = 0;
    for (int j = 0; j < CH; j++) {
        int i = base + j;
        if (i < N_NODES) s += g_deg[i];
    }
    sm[t] = s;
    __syncthreads();
    for (int d = 1; d < 1024; d <<= 1) {
        int v = (t >= d) ? sm[t - d] : 0;
        __syncthreads();
        sm[t] += v;
        __syncthreads();
    }
    int run = sm[t] - s;
    for (int j = 0; j < CH; j++) {
        int i = base + j;
        if (i < N_NODES) { g_off[i] = run; run += g_deg[i]; }
    }
    if (t == 1023) g_off[N_NODES] = run;
}
__global__ void k_scatter(const int* __restrict__ src, const int* __restrict__ dst,
                          const float* __restrict__ p) {
    int e = blockIdx.x * blockDim.x + threadIdx.x;
    if (e >= N_EDGES) return;
    int d = dst[e];
    int pos = atomicAdd(&g_cur[d], 1);
    int idx = g_off[d] + pos;
    g_edge[idx] = make_float2(__int_as_float(src[e]), p[e]);
}

// ---------------- all weight prep in ONE kernel ------------------------------
__global__ void k_wprep(const float* __restrict__ W1, const float* __restrict__ R1w,
                        const float* __restrict__ Wa, const float* __restrict__ Ra,
                        const float* __restrict__ Wb, const float* __restrict__ Rb,
                        const float* __restrict__ W2, const float* __restrict__ R2w) {
    int i = blockIdx.x * blockDim.x + threadIdx.x;
    if (i < KD1 * NH) {
        int k = i >> 6, c = i & 63;
        float v;
        if (k < NF)            v = W1[k * 64 + c];
        else if (k < 2 * NF)   v = W1[(NF + (k - NF)) * 64 + c] - W1[(k - NF) * 64 + c];
        else                   v = R1w[(k - 2 * NF) * 64 + c];
        g_Wcat1[i] = v;
        return;
    }
    i -= KD1 * NH;
    if (i < 2 * KD * NH) {
        const float* W = (i < KD * NH) ? Wa : Wb;
        const float* R = (i < KD * NH) ? Ra : Rb;
        float* out     = (i < KD * NH) ? g_WtA : g_WtB;
        int t = i % (KD * NH);
        int k2 = t >> 7, rem = t & 127, c = rem >> 1, j = rem & 1;
        int kk = 2 * k2 + j;
        float v;
        if (kk < NH)           v = W[kk * 64 + c];
        else if (kk < 2 * NH)  v = W[(NH + (kk - NH)) * 64 + c] - W[(kk - NH) * 64 + c];
        else                   v = R[(kk - 2 * NH) * 64 + c];
        out[t] = v;
        return;
    }
    i -= 2 * KD * NH;
    if (i < KD * NC) {
        int k = i >> 4, c = i & 15;
        float v;
        if (k < NH)            v = W2[k * 16 + c];
        else if (k < 2 * NH)   v = W2[(NH + (k - NH)) * 16 + c] - W2[(k - NH) * 16 + c];
        else                   v = R2w[(k - 2 * NH) * 16 + c];
        g_Wcat2[i] = v;
    }
}

// ---------------- conv1 dense GEMM (packed f32x2), 3 col-segments ----------
// seg = blockIdx.y: 0 -> x@W0 into XG bits0, 1 -> x@D into XG bits1, 2 -> x@R into XR
__global__ void __launch_bounds__(256) k_gemm192(const float* __restrict__ X) {
    __shared__ __align__(16) float As[16][132];
    __shared__ __align__(16) float Bs[16][64];
    int tid  = threadIdx.x;
    int row0 = blockIdx.x * 128;
    int seg  = blockIdx.y;
    const float* Wseg = g_Wcat1 + seg * NF * 64;
    int tx = tid & 7, ty = tid >> 3;
    u64 acc[4][4];
#pragma unroll
    for (int i = 0; i < 4; i++)
#pragma unroll
        for (int j = 0; j < 4; j++) acc[i][j] = 0ULL;
    int c  = tid & 15;
    int rb = tid >> 4;
#pragma unroll 1
    for (int kk = 0; kk < NF; kk += 16) {
#pragma unroll
        for (int i = 0; i < 8; i++) {
            int r = i * 16 + rb;
            int grow = row0 + r;
            As[c][r] = (grow < N_NODES) ? X[grow * NF + kk + c] : 0.f;
        }
#pragma unroll
        for (int i = 0; i < 4; i++) {
            int idx = tid + i * 256;
            Bs[idx >> 6][idx & 63] = Wseg[(kk + (idx >> 6)) * 64 + (idx & 63)];
        }
        __syncthreads();
#pragma unroll
        for (int k = 0; k < 16; k++) {
            float4 aa = *(const float4*)&As[k][ty * 4];
            ulonglong2 w01 = *(const ulonglong2*)&Bs[k][tx * 8];
            ulonglong2 w23 = *(const ulonglong2*)&Bs[k][tx * 8 + 4];
            u64 ap[4] = {pack2_dup(aa.x), pack2_dup(aa.y),
                         pack2_dup(aa.z), pack2_dup(aa.w)};
            u64 bp[4] = {w01.x, w01.y, w23.x, w23.y};
#pragma unroll
            for (int i = 0; i < 4; i++)
#pragma unroll
                for (int j = 0; j < 4; j++) ffma2(acc[i][j], ap[i], bp[j]);
        }
        __syncthreads();
    }
#pragma unroll
    for (int i = 0; i < 4; i++) {
        int grow = row0 + ty * 4 + i;
        if (grow < N_NODES) {
#pragma unroll
            for (int j = 0; j < 4; j++) {
                int c0 = tx * 4 + j;      // channel-pair index (cols 2c0, 2c0+1)
                float lo, hi;
                unpack2(acc[i][j], lo, hi);
                if (seg < 2)
                    *(float2*)&g_XG[grow * 128 + 4 * c0 + 2 * seg] = make_float2(lo, hi);
                else
                    *(float2*)&g_XR[grow * 64 + 2 * c0] = make_float2(lo, hi);
            }
        }
    }
}

// ---------------- conv1 gather on [xW0|xD] pairs + bias + tanh -> h ---------
__global__ void __launch_bounds__(256) k_cagg1(const float* __restrict__ b1,
                                               float* __restrict__ H) {
    __shared__ float2 Stg[8][32];
    int wid = threadIdx.x >> 5, lane = threadIdx.x & 31;
    int node = blockIdx.x * 8 + wid;
    if (node >= N_NODES) return;
    int s0 = g_off[node], s1 = g_off[node + 1];
    const float4* G4 = (const float4*)g_XG;
    float2* stg = Stg[wid];
    float u0x = 0.f, u0y = 0.f, u1x = 0.f, u1y = 0.f;
    for (int e0 = s0; e0 < s1; e0 += 32) {
        int e = e0 + lane;
        if (e < s1) stg[lane] = g_edge[e];
        __syncwarp();
        int cnt = min(32, s1 - e0);
        int j = 0;
        for (; j + 4 <= cnt; j += 4) {
            float2 eA = stg[j], eB = stg[j + 1], eC = stg[j + 2], eD = stg[j + 3];
            float4 vA = G4[__float_as_int(eA.x) * 32 + lane];
            float4 vB = G4[__float_as_int(eB.x) * 32 + lane];
            float4 vC = G4[__float_as_int(eC.x) * 32 + lane];
            float4 vD = G4[__float_as_int(eD.x) * 32 + lane];
            u0x += (vA.x + vB.x) + (vC.x + vD.x);
            u0y += (vA.y + vB.y) + (vC.y + vD.y);
            u1x += eA.y * vA.z + eB.y * vB.z + eC.y * vC.z + eD.y * vD.z;
            u1y += eA.y * vA.w + eB.y * vB.w + eC.y * vC.w + eD.y * vD.w;
        }
        for (; j < cnt; j++) {
            float2 ev = stg[j];
            float4 v = G4[__float_as_int(ev.x) * 32 + lane];
            u0x += v.x; u0y += v.y;
            u1x += ev.y * v.z; u1y += ev.y * v.w;
        }
        __syncwarp();
    }
    float inv = 1.0f / (float)max(s1 - s0, 1);
    float2 xr = ((const float2*)g_XR)[node * 32 + lane];
    float vA = (u0x + u1x) * inv + xr.x + b1[2 * lane];
    float vB = (u0y + u1y) * inv + xr.y + b1[2 * lane + 1];
    ((float2*)H)[node * 32 + lane] = make_float2(tanhf(vA), tanhf(vB));
}

// ---- staged gather for one node: lane owns channels {2l,2l+1} --------------
__device__ __forceinline__ void gather_node(
        const float2* __restrict__ X2, float2* __restrict__ stg,
        int lane, int s0, int s1,
        float& u0x, float& u0y, float& u1x, float& u1y) {
    u0x = 0.f; u0y = 0.f; u1x = 0.f; u1y = 0.f;
    for (int e0 = s0; e0 < s1; e0 += 32) {
        int e = e0 + lane;
        if (e < s1) stg[lane] = g_edge[e];
        __syncwarp();
        int cnt = min(32, s1 - e0);
        int j = 0;
        for (; j + 4 <= cnt; j += 4) {
            float2 eA = stg[j], eB = stg[j + 1], eC = stg[j + 2], eD = stg[j + 3];
            float2 vA = X2[__float_as_int(eA.x) * 32 + lane];
            float2 vB = X2[__float_as_int(eB.x) * 32 + lane];
            float2 vC = X2[__float_as_int(eC.x) * 32 + lane];
            float2 vD = X2[__float_as_int(eD.x) * 32 + lane];
            u0x += (vA.x + vB.x) + (vC.x + vD.x);
            u0y += (vA.y + vB.y) + (vC.y + vD.y);
            u1x += eA.y * vA.x + eB.y * vB.x + eC.y * vC.x + eD.y * vD.x;
            u1y += eA.y * vA.y + eB.y * vB.y + eC.y * vC.y + eD.y * vD.y;
        }
        for (; j < cnt; j++) {
            float2 ev = stg[j];
            float2 v = X2[__float_as_int(ev.x) * 32 + lane];
            u0x += v.x; u0y += v.y;
            u1x += ev.y * v.x; u1y += ev.y * v.y;
        }
        __syncwarp();
    }
}

// ---------------- FUSED hidden conv (work-stealing octets) ------------------
// MODE 0: Yout = conv(Xin)
// MODE 1: Yout = conv(Xin);  Yaux = H + cmul * Yout
// MODE 2: Yaux = H + 0.5*(k1 + 2 k2 + 2 k3 + conv(Xin))
template <int MODE>
__global__ void __launch_bounds__(256, 2) k_conv64f(
        const float* __restrict__ Xin, const float* __restrict__ Wt,
        const float* __restrict__ bias,
        float* __restrict__ Yout, float* __restrict__ Yaux,
        const float* __restrict__ H, float cmul, int slot) {
    extern __shared__ float sm[];
    float* Ws = sm;                                // KD*64 floats
    float* Sa = sm + KD * 64;                      // 8 warps * 8 nodes * KD
    float2* stgAll = (float2*)(sm + 2 * KD * 64);  // 8 warps * 32 float2
    for (int i = threadIdx.x; i < KD * 64; i += 256) Ws[i] = Wt[i];
    __syncthreads();

    int wid = threadIdx.x >> 5, lane = threadIdx.x & 31;
    float* myA  = Sa + wid * (8 * KD);
    float2* stg = stgAll + wid * 32;
    const float2* X2 = (const float2*)Xin;
    float bs0 = bias[2 * lane], bs1 = bias[2 * lane + 1];

    while (true) {
        int o;
        if (lane == 0) o = atomicAdd(&g_wctr[slot], 1);
        o = __shfl_sync(0xffffffffu, o, 0);
        if (o >= N_OCT) break;
        int base = o * 8;
        // ---- gather phase ----
        for (int n = 0; n < 8; n++) {
            int node = base + n;
            int s0 = g_off[node], s1 = g_off[node + 1];
            float u0x, u0y, u1x, u1y;
            gather_node(X2, stg, lane, s0, s1, u0x, u0y, u1x, u1y);
            float inv = 1.0f / (float)max(s1 - s0, 1);
            float2 xv = X2[node * 32 + lane];
            float* an = myA + n * KD;
            an[2 * lane]           = u0x * inv;
            an[2 * lane + 1]       = u0y * inv;
            an[64 + 2 * lane]      = u1x * inv;
            an[64 + 2 * lane + 1]  = u1y * inv;
            an[128 + 2 * lane]     = xv.x;
            an[128 + 2 * lane + 1] = xv.y;
        }
        __syncwarp();
        // ---- FMA phase: lane owns cols {2l, 2l+1}; packed over k-pairs ----
        u64 accA[8], accB[8];
#pragma unroll
        for (int n = 0; n < 8; n++) { accA[n] = 0ULL; accB[n] = 0ULL; }
#pragma unroll 2
        for (int k2 = 0; k2 < KD / 2; k2 += 2) {
            ulonglong2 w0 = *(const ulonglong2*)&Ws[k2 * 128 + lane * 4];
            ulonglong2 w1 = *(const ulonglong2*)&Ws[(k2 + 1) * 128 + lane * 4];
#pragma unroll
            for (int n = 0; n < 8; n++) {
                ulonglong2 av = *(const ulonglong2*)&myA[n * KD + 2 * k2];
                ffma2(accA[n], av.x, w0.x);
                ffma2(accB[n], av.x, w0.y);
                ffma2(accA[n], av.y, w1.x);
                ffma2(accB[n], av.y, w1.y);
            }
        }
        // ---- epilogue ----
        for (int n = 0; n < 8; n++) {
            int node = base + n;
            float aLo, aHi, bLo, bHi;
            unpack2(accA[n], aLo, aHi);
            unpack2(accB[n], bLo, bHi);
            float vA = aLo + aHi + bs0;
            float vB = bLo + bHi + bs1;
            if (MODE == 0) {
                ((float2*)Yout)[node * 32 + lane] = make_float2(vA, vB);
            } else if (MODE == 1) {
                ((float2*)Yout)[node * 32 + lane] = make_float2(vA, vB);
                float2 h2 = ((const float2*)H)[node * 32 + lane];
                ((float2*)Yaux)[node * 32 + lane] =
                    make_float2(h2.x + cmul * vA, h2.y + cmul * vB);
            } else {
                float2 h2 = ((const float2*)H)[node * 32 + lane];
                float2 a1 = ((const float2*)g_k1)[node * 32 + lane];
                float2 a2 = ((const float2*)g_k2)[node * 32 + lane];
                float2 a3 = ((const float2*)g_k3)[node * 32 + lane];
                ((float2*)Yaux)[node * 32 + lane] = make_float2(
                    h2.x + 0.5f * (a1.x + 2.f * a2.x + 2.f * a3.x + vA),
                    h2.y + 0.5f * (a1.y + 2.f * a2.y + 2.f * a3.y + vB));
            }
        }
        __syncwarp();
    }
}

// ---------------- FUSED final conv + tanh + log_softmax ---------------------
__global__ void __launch_bounds__(256) k_conv16f(
        const float* __restrict__ Yin, const float* __restrict__ b2,
        float* __restrict__ out) {
    __shared__ float  Ws[KD * NC];
    __shared__ float  Sa[8][KD];
    __shared__ float2 Stg[8][32];
    for (int i = threadIdx.x; i < KD * NC; i += 256) Ws[i] = g_Wcat2[i];
    __syncthreads();
    int wid = threadIdx.x >> 5, lane = threadIdx.x & 31;
    int node = blockIdx.x * 8 + wid;
    if (node >= N_NODES) return;
    const float2* X2 = (const float2*)Yin;
    int s0 = g_off[node], s1 = g_off[node + 1];
    float u0x, u0y, u1x, u1y;
    gather_node(X2, Stg[wid], lane, s0, s1, u0x, u0y, u1x, u1y);
    float inv = 1.0f / (float)max(s1 - s0, 1);
    float2 xv = X2[node * 32 + lane];
    Sa[wid][2 * lane]           = u0x * inv;
    Sa[wid][2 * lane + 1]       = u0y * inv;
    Sa[wid][64 + 2 * lane]      = u1x * inv;
    Sa[wid][64 + 2 * lane + 1]  = u1y * inv;
    Sa[wid][128 + 2 * lane]     = xv.x;
    Sa[wid][128 + 2 * lane + 1] = xv.y;
    __syncwarp();
    int half = lane >> 4, c = lane & 15;
    const float* a = &Sa[wid][96 * half];
    const float* w = &Ws[(96 * half) * 16 + c];
    float acc = 0.f;
#pragma unroll 4
    for (int k = 0; k < 96; k++) acc += a[k] * w[k * 16];
    acc += __shfl_down_sync(0xffffffffu, acc, 16);
    float v = tanhf(acc + b2[c]);
    float m = v;
#pragma unroll
    for (int off = 8; off; off >>= 1) m = fmaxf(m, __shfl_xor_sync(0xffffffffu, m, off));
    float s = expf(v - m);
#pragma unroll
    for (int off = 8; off; off >>= 1) s += __shfl_xor_sync(0xffffffffu, s, off);
    float lse = m + logf(s);
    if (lane < 16) out[node * 16 + c] = v - lse;
}

// ---------------- driver -----------------------------------------------------
extern "C" void kernel_launch(void* const* d_in, const int* in_sizes, int n_in,
                              void* d_out, int out_size) {
    const float* x   = (const float*)d_in[0];
    const float* p   = (const float*)d_in[1];
    const int*   src = (const int*)  d_in[2];
    const int*   dst = (const int*)  d_in[3];
    const float* W1  = (const float*)d_in[4];
    const float* R1  = (const float*)d_in[5];
    const float* b1  = (const float*)d_in[6];
    const float* Wa  = (const float*)d_in[7];
    const float* Ra  = (const float*)d_in[8];
    const float* ba  = (const float*)d_in[9];
    const float* Wb  = (const float*)d_in[10];
    const float* Rb  = (const float*)d_in[11];
    const float* bb  = (const float*)d_in[12];
    const float* W2  = (const float*)d_in[13];
    const float* R2  = (const float*)d_in[14];
    const float* b2  = (const float*)d_in[15];
    float* out = (float*)d_out;

    void* tmp;
    float *ph, *py, *pt, *pk1, *pk2, *pk3, *pWtA, *pWtB;
    cudaGetSymbolAddress(&tmp, g_h);   ph  = (float*)tmp;
    cudaGetSymbolAddress(&tmp, g_y);   py  = (float*)tmp;
    cudaGetSymbolAddress(&tmp, g_t);   pt  = (float*)tmp;
    cudaGetSymbolAddress(&tmp, g_k1);  pk1 = (float*)tmp;
    cudaGetSymbolAddress(&tmp, g_k2);  pk2 = (float*)tmp;
    cudaGetSymbolAddress(&tmp, g_k3);  pk3 = (float*)tmp;
    cudaGetSymbolAddress(&tmp, g_WtA); pWtA = (float*)tmp;
    cudaGetSymbolAddress(&tmp, g_WtB); pWtB = (float*)tmp;

    const int SMB = (2 * KD * 64 + 512) * 4;   // 100352 bytes
    cudaFuncSetAttribute(k_conv64f<0>, cudaFuncAttributeMaxDynamicSharedMemorySize, SMB);
    cudaFuncSetAttribute(k_conv64f<1>, cudaFuncAttributeMaxDynamicSharedMemorySize, SMB);
    cudaFuncSetAttribute(k_conv64f<2>, cudaFuncAttributeMaxDynamicSharedMemorySize, SMB);

    const int EB = (N_EDGES + 255) / 256;
    const int NB = (N_NODES + 255) / 256;
    const int WB = (N_NODES + 7) / 8;   // block per 8 nodes (warp per node)
    const int CG = 296;                 // persistent, 2 blocks/SM

    // CSR build
    k_zero<<<NB, 256>>>();
    k_hist<<<EB, 256>>>(dst);
    k_scan<<<1, 1024>>>();
    k_scatter<<<EB, 256>>>(src, dst, p);

    // all weight prep (one launch)
    k_wprep<<<(KD1 * NH + 2 * KD * NH + KD * NC + 255) / 256, 256>>>(
        W1, R1, Wa, Ra, Wb, Rb, W2, R2);

    // conv1 GEMM-first: XG = x@[W0|D] (interleaved), XR = x@R ; then gather
    {
        dim3 g((N_NODES + 127) / 128, 3);
        k_gemm192<<<g, 256>>>(x);
    }
    k_cagg1<<<WB, 256>>>(b1, ph);

    // RK4 (T=3): k_i from fused double-conv, axpy folded into epilogues
    k_conv64f<0><<<CG, 256, SMB>>>(ph, pWtA, ba, pt, nullptr, nullptr, 0.f, 0);
    k_conv64f<1><<<CG, 256, SMB>>>(pt, pWtB, bb, pk1, py, ph, 1.5f, 1);
    k_conv64f<0><<<CG, 256, SMB>>>(py, pWtA, ba, pt, nullptr, nullptr, 0.f, 2);
    k_conv64f<1><<<CG, 256, SMB>>>(pt, pWtB, bb, pk2, py, ph, 1.5f, 3);
    k_conv64f<0><<<CG, 256, SMB>>>(py, pWtA, ba, pt, nullptr, nullptr, 0.f, 4);
    k_conv64f<1><<<CG, 256, SMB>>>(pt, pWtB, bb, pk3, py, ph, 3.0f, 5);
    k_conv64f<0><<<CG, 256, SMB>>>(py, pWtA, ba, pt, nullptr, nullptr, 0.f, 6);
    k_conv64f<2><<<CG, 256, SMB>>>(pt, pWtB, bb, pt, py, ph, 0.f, 7);

    // conv2 + tanh + log_softmax -> out
    k_conv16f<<<WB, 256>>>(py, b2, out);
}

// round 10
// speedup vs baseline: 1.5378x; 1.5378x over previous
#include <cuda_runtime.h>
#include <math.h>

#define N_NODES 50000
#define N_EDGES 800000
#define NF 256
#define NH 64
#define NC 16
#define KD 192      // 3*NH
#define KD1 768     // 3*NF

// ---------------- scratch (device globals) ----------------------------------
__device__ float g_XG[N_NODES * 128];  // conv1 gemm-first: interleaved [xW0|xD] pairs
__device__ float g_XR[N_NODES * NH];   // conv1: x @ R1
__device__ float g_h [N_NODES * NH];
__device__ float g_y [N_NODES * NH];
__device__ float g_t [N_NODES * NH];
__device__ float g_k1[N_NODES * NH];
__device__ float g_k2[N_NODES * NH];
__device__ float g_k3[N_NODES * NH];
__device__ float g_Wcat1[KD1 * NH];   // conv1 [768,64]: rows 0-255 W0, 256-511 D, 512-767 R
__device__ float g_WtA[KD * NH];      // hidden conv A, pair-transposed
__device__ float g_WtB[KD * NH];      // hidden conv B, pair-transposed
__device__ float g_Wcat2[KD * NC];    // final conv plain [192,16]
__device__ int    g_off[N_NODES + 1];
__device__ int    g_deg[N_NODES];
__device__ int    g_cur[N_NODES];
__device__ float2 g_edge[N_EDGES];    // (src-as-float-bits, p)

// ---------------- packed f32x2 helpers --------------------------------------
typedef unsigned long long u64;
__device__ __forceinline__ void ffma2(u64& d, u64 a, u64 b) {
    asm("fma.rn.f32x2 %0, %1, %2, %0;" : "+l"(d) : "l"(a), "l"(b));
}
__device__ __forceinline__ u64 pack2_dup(float x) {
    u64 r;
    unsigned int u = __float_as_uint(x);
    asm("mov.b64 %0, {%1, %1};" : "=l"(r) : "r"(u));
    return r;
}
__device__ __forceinline__ void unpack2(u64 v, float& lo, float& hi) {
    unsigned int a, b;
    asm("mov.b64 {%0, %1}, %2;" : "=r"(a), "=r"(b) : "l"(v));
    lo = __uint_as_float(a);
    hi = __uint_as_float(b);
}

// ---------------- CSR build --------------------------------------------------
__global__ void k_zero() {
    int i = blockIdx.x * blockDim.x + threadIdx.x;
    if (i < N_NODES) { g_deg[i] = 0; g_cur[i] = 0; }
}
__global__ void k_hist(const int* __restrict__ dst) {
    int e = blockIdx.x * blockDim.x + threadIdx.x;
    if (e < N_EDGES) atomicAdd(&g_deg[dst[e]], 1);
}
__global__ void k_scan() {
    __shared__ int sm[1024];
    int t = threadIdx.x;
    const int CH = (N_NODES + 1023) / 1024;
    int base = t * CH;
    int s = 0;
    for (int j = 0; j < CH; j++) {
        int i = base + j;
        if (i < N_NODES) s += g_deg[i];
    }
    sm[t] = s;
    __syncthreads();
    for (int d = 1; d < 1024; d <<= 1) {
        int v = (t >= d) ? sm[t - d] : 0;
        __syncthreads();
        sm[t] += v;
        __syncthreads();
    }
    int run = sm[t] - s;
    for (int j = 0; j < CH; j++) {
        int i = base + j;
        if (i < N_NODES) { g_off[i] = run; run += g_deg[i]; }
    }
    if (t == 1023) g_off[N_NODES] = run;
}
__global__ void k_scatter(const int* __restrict__ src, const int* __restrict__ dst,
                          const float* __restrict__ p) {
    int e = blockIdx.x * blockDim.x + threadIdx.x;
    if (e >= N_EDGES) return;
    int d = dst[e];
    int pos = atomicAdd(&g_cur[d], 1);
    int idx = g_off[d] + pos;
    g_edge[idx] = make_float2(__int_as_float(src[e]), p[e]);
}

// ---------------- all weight prep in ONE kernel ------------------------------
__global__ void k_wprep(const float* __restrict__ W1, const float* __restrict__ R1w,
                        const float* __restrict__ Wa, const float* __restrict__ Ra,
                        const float* __restrict__ Wb, const float* __restrict__ Rb,
                        const float* __restrict__ W2, const float* __restrict__ R2w) {
    int i = blockIdx.x * blockDim.x + threadIdx.x;
    if (i < KD1 * NH) {
        int k = i >> 6, c = i & 63;
        float v;
        if (k < NF)            v = W1[k * 64 + c];
        else if (k < 2 * NF)   v = W1[(NF + (k - NF)) * 64 + c] - W1[(k - NF) * 64 + c];
        else                   v = R1w[(k - 2 * NF) * 64 + c];
        g_Wcat1[i] = v;
        return;
    }
    i -= KD1 * NH;
    if (i < 2 * KD * NH) {
        const float* W = (i < KD * NH) ? Wa : Wb;
        const float* R = (i < KD * NH) ? Ra : Rb;
        float* out     = (i < KD * NH) ? g_WtA : g_WtB;
        int t = i % (KD * NH);
        int k2 = t >> 7, rem = t & 127, c = rem >> 1, j = rem & 1;
        int kk = 2 * k2 + j;
        float v;
        if (kk < NH)           v = W[kk * 64 + c];
        else if (kk < 2 * NH)  v = W[(NH + (kk - NH)) * 64 + c] - W[(kk - NH) * 64 + c];
        else                   v = R[(kk - 2 * NH) * 64 + c];
        out[t] = v;
        return;
    }
    i -= 2 * KD * NH;
    if (i < KD * NC) {
        int k = i >> 4, c = i & 15;
        float v;
        if (k < NH)            v = W2[k * 16 + c];
        else if (k < 2 * NH)   v = W2[(NH + (k - NH)) * 16 + c] - W2[(k - NH) * 16 + c];
        else                   v = R2w[(k - 2 * NH) * 16 + c];
        g_Wcat2[i] = v;
    }
}

// ---------------- conv1 dense GEMM (packed f32x2), 3 col-segments ----------
// seg = blockIdx.y: 0 -> x@W0 into XG bits0, 1 -> x@D into XG bits1, 2 -> x@R into XR
__global__ void __launch_bounds__(256) k_gemm192(const float* __restrict__ X) {
    __shared__ __align__(16) float As[16][132];
    __shared__ __align__(16) float Bs[16][64];
    int tid  = threadIdx.x;
    int row0 = blockIdx.x * 128;
    int seg  = blockIdx.y;
    const float* Wseg = g_Wcat1 + seg * NF * 64;
    int tx = tid & 7, ty = tid >> 3;
    u64 acc[4][4];
#pragma unroll
    for (int i = 0; i < 4; i++)
#pragma unroll
        for (int j = 0; j < 4; j++) acc[i][j] = 0ULL;
    int c  = tid & 15;
    int rb = tid >> 4;
#pragma unroll 1
    for (int kk = 0; kk < NF; kk += 16) {
#pragma unroll
        for (int i = 0; i < 8; i++) {
            int r = i * 16 + rb;
            int grow = row0 + r;
            As[c][r] = (grow < N_NODES) ? X[grow * NF + kk + c] : 0.f;
        }
#pragma unroll
        for (int i = 0; i < 4; i++) {
            int idx = tid + i * 256;
            Bs[idx >> 6][idx & 63] = Wseg[(kk + (idx >> 6)) * 64 + (idx & 63)];
        }
        __syncthreads();
#pragma unroll
        for (int k = 0; k < 16; k++) {
            float4 aa = *(const float4*)&As[k][ty * 4];
            ulonglong2 w01 = *(const ulonglong2*)&Bs[k][tx * 8];
            ulonglong2 w23 = *(const ulonglong2*)&Bs[k][tx * 8 + 4];
            u64 ap[4] = {pack2_dup(aa.x), pack2_dup(aa.y),
                         pack2_dup(aa.z), pack2_dup(aa.w)};
            u64 bp[4] = {w01.x, w01.y, w23.x, w23.y};
#pragma unroll
            for (int i = 0; i < 4; i++)
#pragma unroll
                for (int j = 0; j < 4; j++) ffma2(acc[i][j], ap[i], bp[j]);
        }
        __syncthreads();
    }
#pragma unroll
    for (int i = 0; i < 4; i++) {
        int grow = row0 + ty * 4 + i;
        if (grow < N_NODES) {
#pragma unroll
            for (int j = 0; j < 4; j++) {
                int c0 = tx * 4 + j;      // channel-pair index (cols 2c0, 2c0+1)
                float lo, hi;
                unpack2(acc[i][j], lo, hi);
                if (seg < 2)
                    *(float2*)&g_XG[grow * 128 + 4 * c0 + 2 * seg] = make_float2(lo, hi);
                else
                    *(float2*)&g_XR[grow * 64 + 2 * c0] = make_float2(lo, hi);
            }
        }
    }
}

// ---------------- conv1 gather on [xW0|xD] pairs + bias + tanh -> h ---------
__global__ void __launch_bounds__(256) k_cagg1(const float* __restrict__ b1,
                                               float* __restrict__ H) {
    __shared__ float2 Stg[8][32];
    int wid = threadIdx.x >> 5, lane = threadIdx.x & 31;
    int node = blockIdx.x * 8 + wid;
    if (node >= N_NODES) return;
    int s0 = g_off[node], s1 = g_off[node + 1];
    const float4* G4 = (const float4*)g_XG;
    float2* stg = Stg[wid];
    float u0x = 0.f, u0y = 0.f, u1x = 0.f, u1y = 0.f;
    for (int e0 = s0; e0 < s1; e0 += 32) {
        int e = e0 + lane;
        if (e < s1) stg[lane] = g_edge[e];
        __syncwarp();
        int cnt = min(32, s1 - e0);
        int j = 0;
        for (; j + 4 <= cnt; j += 4) {
            float2 eA = stg[j], eB = stg[j + 1], eC = stg[j + 2], eD = stg[j + 3];
            float4 vA = G4[__float_as_int(eA.x) * 32 + lane];
            float4 vB = G4[__float_as_int(eB.x) * 32 + lane];
            float4 vC = G4[__float_as_int(eC.x) * 32 + lane];
            float4 vD = G4[__float_as_int(eD.x) * 32 + lane];
            u0x += (vA.x + vB.x) + (vC.x + vD.x);
            u0y += (vA.y + vB.y) + (vC.y + vD.y);
            u1x += eA.y * vA.z + eB.y * vB.z + eC.y * vC.z + eD.y * vD.z;
            u1y += eA.y * vA.w + eB.y * vB.w + eC.y * vC.w + eD.y * vD.w;
        }
        for (; j < cnt; j++) {
            float2 ev = stg[j];
            float4 v = G4[__float_as_int(ev.x) * 32 + lane];
            u0x += v.x; u0y += v.y;
            u1x += ev.y * v.z; u1y += ev.y * v.w;
        }
        __syncwarp();
    }
    float inv = 1.0f / (float)max(s1 - s0, 1);
    float2 xr = ((const float2*)g_XR)[node * 32 + lane];
    float vA = (u0x + u1x) * inv + xr.x + b1[2 * lane];
    float vB = (u0y + u1y) * inv + xr.y + b1[2 * lane + 1];
    ((float2*)H)[node * 32 + lane] = make_float2(tanhf(vA), tanhf(vB));
}

// ---- staged gather for one node: lane owns channels {2l,2l+1} --------------
__device__ __forceinline__ void gather_node(
        const float2* __restrict__ X2, float2* __restrict__ stg,
        int lane, int s0, int s1,
        float& u0x, float& u0y, float& u1x, float& u1y) {
    u0x = 0.f; u0y = 0.f; u1x = 0.f; u1y = 0.f;
    for (int e0 = s0; e0 < s1; e0 += 32) {
        int e = e0 + lane;
        if (e < s1) stg[lane] = g_edge[e];
        __syncwarp();
        int cnt = min(32, s1 - e0);
        int j = 0;
        for (; j + 4 <= cnt; j += 4) {
            float2 eA = stg[j], eB = stg[j + 1], eC = stg[j + 2], eD = stg[j + 3];
            float2 vA = X2[__float_as_int(eA.x) * 32 + lane];
            float2 vB = X2[__float_as_int(eB.x) * 32 + lane];
            float2 vC = X2[__float_as_int(eC.x) * 32 + lane];
            float2 vD = X2[__float_as_int(eD.x) * 32 + lane];
            u0x += (vA.x + vB.x) + (vC.x + vD.x);
            u0y += (vA.y + vB.y) + (vC.y + vD.y);
            u1x += eA.y * vA.x + eB.y * vB.x + eC.y * vC.x + eD.y * vD.x;
            u1y += eA.y * vA.y + eB.y * vB.y + eC.y * vC.y + eD.y * vD.y;
        }
        for (; j < cnt; j++) {
            float2 ev = stg[j];
            float2 v = X2[__float_as_int(ev.x) * 32 + lane];
            u0x += v.x; u0y += v.y;
            u1x += ev.y * v.x; u1y += ev.y * v.y;
        }
        __syncwarp();
    }
}

// ---------------- FUSED hidden conv (static grid-stride octets) -------------
// MODE 0: Yout = conv(Xin)
// MODE 1: Yout = conv(Xin);  Yaux = H + cmul * Yout
// MODE 2: Yaux = H + 0.5*(k1 + 2 k2 + 2 k3 + conv(Xin))
template <int MODE>
__global__ void __launch_bounds__(256, 2) k_conv64f(
        const float* __restrict__ Xin, const float* __restrict__ Wt,
        const float* __restrict__ bias,
        float* __restrict__ Yout, float* __restrict__ Yaux,
        const float* __restrict__ H, float cmul) {
    extern __shared__ float sm[];
    float* Ws = sm;                                // KD*64 floats
    float* Sa = sm + KD * 64;                      // 8 warps * 8 nodes * KD
    float2* stgAll = (float2*)(sm + 2 * KD * 64);  // 8 warps * 32 float2
    for (int i = threadIdx.x; i < KD * 64; i += 256) Ws[i] = Wt[i];
    __syncthreads();

    int wid = threadIdx.x >> 5, lane = threadIdx.x & 31;
    float* myA  = Sa + wid * (8 * KD);
    float2* stg = stgAll + wid * 32;
    const float2* X2 = (const float2*)Xin;
    float bs0 = bias[2 * lane], bs1 = bias[2 * lane + 1];

    int gw0    = (blockIdx.x * 8 + wid) * 8;
    int stride = gridDim.x * 64;
    for (int base = gw0; base < N_NODES; base += stride) {
        int nn = min(8, N_NODES - base);
        // ---- gather phase ----
        for (int n = 0; n < nn; n++) {
            int node = base + n;
            int s0 = g_off[node], s1 = g_off[node + 1];
            float u0x, u0y, u1x, u1y;
            gather_node(X2, stg, lane, s0, s1, u0x, u0y, u1x, u1y);
            float inv = 1.0f / (float)max(s1 - s0, 1);
            float2 xv = X2[node * 32 + lane];
            float* an = myA + n * KD;
            an[2 * lane]           = u0x * inv;
            an[2 * lane + 1]       = u0y * inv;
            an[64 + 2 * lane]      = u1x * inv;
            an[64 + 2 * lane + 1]  = u1y * inv;
            an[128 + 2 * lane]     = xv.x;
            an[128 + 2 * lane + 1] = xv.y;
        }
        __syncwarp();
        // ---- FMA phase: lane owns cols {2l, 2l+1}; packed over k-pairs ----
        u64 accA[8], accB[8];
#pragma unroll
        for (int n = 0; n < 8; n++) { accA[n] = 0ULL; accB[n] = 0ULL; }
#pragma unroll 2
        for (int k2 = 0; k2 < KD / 2; k2 += 2) {
            ulonglong2 w0 = *(const ulonglong2*)&Ws[k2 * 128 + lane * 4];
            ulonglong2 w1 = *(const ulonglong2*)&Ws[(k2 + 1) * 128 + lane * 4];
#pragma unroll
            for (int n = 0; n < 8; n++) {
                ulonglong2 av = *(const ulonglong2*)&myA[n * KD + 2 * k2];
                ffma2(accA[n], av.x, w0.x);
                ffma2(accB[n], av.x, w0.y);
                ffma2(accA[n], av.y, w1.x);
                ffma2(accB[n], av.y, w1.y);
            }
        }
        // ---- epilogue ----
        for (int n = 0; n < nn; n++) {
            int node = base + n;
            float aLo, aHi, bLo, bHi;
            unpack2(accA[n], aLo, aHi);
            unpack2(accB[n], bLo, bHi);
            float vA = aLo + aHi + bs0;
            float vB = bLo + bHi + bs1;
            if (MODE == 0) {
                ((float2*)Yout)[node * 32 + lane] = make_float2(vA, vB);
            } else if (MODE == 1) {
                ((float2*)Yout)[node * 32 + lane] = make_float2(vA, vB);
                float2 h2 = ((const float2*)H)[node * 32 + lane];
                ((float2*)Yaux)[node * 32 + lane] =
                    make_float2(h2.x + cmul * vA, h2.y + cmul * vB);
            } else {
                float2 h2 = ((const float2*)H)[node * 32 + lane];
                float2 a1 = ((const float2*)g_k1)[node * 32 + lane];
                float2 a2 = ((const float2*)g_k2)[node * 32 + lane];
                float2 a3 = ((const float2*)g_k3)[node * 32 + lane];
                ((float2*)Yaux)[node * 32 + lane] = make_float2(
                    h2.x + 0.5f * (a1.x + 2.f * a2.x + 2.f * a3.x + vA),
                    h2.y + 0.5f * (a1.y + 2.f * a2.y + 2.f * a3.y + vB));
            }
        }
        __syncwarp();
    }
}

// ---------------- FUSED final conv + tanh + log_softmax ---------------------
__global__ void __launch_bounds__(256) k_conv16f(
        const float* __restrict__ Yin, const float* __restrict__ b2,
        float* __restrict__ out) {
    __shared__ float  Ws[KD * NC];
    __shared__ float  Sa[8][KD];
    __shared__ float2 Stg[8][32];
    for (int i = threadIdx.x; i < KD * NC; i += 256) Ws[i] = g_Wcat2[i];
    __syncthreads();
    int wid = threadIdx.x >> 5, lane = threadIdx.x & 31;
    int node = blockIdx.x * 8 + wid;
    if (node >= N_NODES) return;
    const float2* X2 = (const float2*)Yin;
    int s0 = g_off[node], s1 = g_off[node + 1];
    float u0x, u0y, u1x, u1y;
    gather_node(X2, Stg[wid], lane, s0, s1, u0x, u0y, u1x, u1y);
    float inv = 1.0f / (float)max(s1 - s0, 1);
    float2 xv = X2[node * 32 + lane];
    Sa[wid][2 * lane]           = u0x * inv;
    Sa[wid][2 * lane + 1]       = u0y * inv;
    Sa[wid][64 + 2 * lane]      = u1x * inv;
    Sa[wid][64 + 2 * lane + 1]  = u1y * inv;
    Sa[wid][128 + 2 * lane]     = xv.x;
    Sa[wid][128 + 2 * lane + 1] = xv.y;
    __syncwarp();
    int half = lane >> 4, c = lane & 15;
    const float* a = &Sa[wid][96 * half];
    const float* w = &Ws[(96 * half) * 16 + c];
    float acc = 0.f;
#pragma unroll 4
    for (int k = 0; k < 96; k++) acc += a[k] * w[k * 16];
    acc += __shfl_down_sync(0xffffffffu, acc, 16);
    float v = tanhf(acc + b2[c]);
    float m = v;
#pragma unroll
    for (int off = 8; off; off >>= 1) m = fmaxf(m, __shfl_xor_sync(0xffffffffu, m, off));
    float s = expf(v - m);
#pragma unroll
    for (int off = 8; off; off >>= 1) s += __shfl_xor_sync(0xffffffffu, s, off);
    float lse = m + logf(s);
    if (lane < 16) out[node * 16 + c] = v - lse;
}

// ---------------- driver -----------------------------------------------------
extern "C" void kernel_launch(void* const* d_in, const int* in_sizes, int n_in,
                              void* d_out, int out_size) {
    const float* x   = (const float*)d_in[0];
    const float* p   = (const float*)d_in[1];
    const int*   src = (const int*)  d_in[2];
    const int*   dst = (const int*)  d_in[3];
    const float* W1  = (const float*)d_in[4];
    const float* R1  = (const float*)d_in[5];
    const float* b1  = (const float*)d_in[6];
    const float* Wa  = (const float*)d_in[7];
    const float* Ra  = (const float*)d_in[8];
    const float* ba  = (const float*)d_in[9];
    const float* Wb  = (const float*)d_in[10];
    const float* Rb  = (const float*)d_in[11];
    const float* bb  = (const float*)d_in[12];
    const float* W2  = (const float*)d_in[13];
    const float* R2  = (const float*)d_in[14];
    const float* b2  = (const float*)d_in[15];
    float* out = (float*)d_out;

    void* tmp;
    float *ph, *py, *pt, *pk1, *pk2, *pk3, *pWtA, *pWtB;
    cudaGetSymbolAddress(&tmp, g_h);   ph  = (float*)tmp;
    cudaGetSymbolAddress(&tmp, g_y);   py  = (float*)tmp;
    cudaGetSymbolAddress(&tmp, g_t);   pt  = (float*)tmp;
    cudaGetSymbolAddress(&tmp, g_k1);  pk1 = (float*)tmp;
    cudaGetSymbolAddress(&tmp, g_k2);  pk2 = (float*)tmp;
    cudaGetSymbolAddress(&tmp, g_k3);  pk3 = (float*)tmp;
    cudaGetSymbolAddress(&tmp, g_WtA); pWtA = (float*)tmp;
    cudaGetSymbolAddress(&tmp, g_WtB); pWtB = (float*)tmp;

    const int SMB = (2 * KD * 64 + 512) * 4;   // 100352 bytes
    cudaFuncSetAttribute(k_conv64f<0>, cudaFuncAttributeMaxDynamicSharedMemorySize, SMB);
    cudaFuncSetAttribute(k_conv64f<1>, cudaFuncAttributeMaxDynamicSharedMemorySize, SMB);
    cudaFuncSetAttribute(k_conv64f<2>, cudaFuncAttributeMaxDynamicSharedMemorySize, SMB);

    const int EB = (N_EDGES + 255) / 256;
    const int NB = (N_NODES + 255) / 256;
    const int WB = (N_NODES + 7) / 8;   // block per 8 nodes (warp per node)
    const int CG = 296;                 // persistent, 2 blocks/SM

    // CSR build
    k_zero<<<NB, 256>>>();
    k_hist<<<EB, 256>>>(dst);
    k_scan<<<1, 1024>>>();
    k_scatter<<<EB, 256>>>(src, dst, p);

    // all weight prep (one launch)
    k_wprep<<<(KD1 * NH + 2 * KD * NH + KD * NC + 255) / 256, 256>>>(
        W1, R1, Wa, Ra, Wb, Rb, W2, R2);

    // conv1 GEMM-first: XG = x@[W0|D] (interleaved), XR = x@R ; then gather
    {
        dim3 g((N_NODES + 127) / 128, 3);
        k_gemm192<<<g, 256>>>(x);
    }
    k_cagg1<<<WB, 256>>>(b1, ph);

    // RK4 (T=3): k_i from fused double-conv, axpy folded into epilogues
    k_conv64f<0><<<CG, 256, SMB>>>(ph, pWtA, ba, pt, nullptr, nullptr, 0.f);
    k_conv64f<1><<<CG, 256, SMB>>>(pt, pWtB, bb, pk1, py, ph, 1.5f);
    k_conv64f<0><<<CG, 256, SMB>>>(py, pWtA, ba, pt, nullptr, nullptr, 0.f);
    k_conv64f<1><<<CG, 256, SMB>>>(pt, pWtB, bb, pk2, py, ph, 1.5f);
    k_conv64f<0><<<CG, 256, SMB>>>(py, pWtA, ba, pt, nullptr, nullptr, 0.f);
    k_conv64f<1><<<CG, 256, SMB>>>(pt, pWtB, bb, pk3, py, ph, 3.0f);
    k_conv64f<0><<<CG, 256, SMB>>>(py, pWtA, ba, pt, nullptr, nullptr, 0.f);
    k_conv64f<2><<<CG, 256, SMB>>>(pt, pWtB, bb, pt, py, ph, 0.f);

    // conv2 + tanh + log_softmax -> out
    k_conv16f<<<WB, 256>>>(py, b2, out);
}

// round 11
// speedup vs baseline: 1.7107x; 1.1124x over previous
#include <cuda_runtime.h>
#include <math.h>

#define N_NODES 50000
#define N_EDGES 800000
#define NF 256
#define NH 64
#define NC 16
#define KD 192      // 3*NH
#define KD1 768     // 3*NF

// ---------------- scratch (device globals) ----------------------------------
__device__ float g_XG[N_NODES * 128];  // conv1 gemm-first: interleaved [xW0|xD] pairs
__device__ float g_XR[N_NODES * NH];   // conv1: x @ R1
__device__ float g_h [N_NODES * NH];
__device__ float g_y [N_NODES * NH];
__device__ float g_t [N_NODES * NH];
__device__ float g_k1[N_NODES * NH];
__device__ float g_k2[N_NODES * NH];
__device__ float g_k3[N_NODES * NH];
__device__ float g_Wcat1[KD1 * NH];   // conv1 [768,64]: rows 0-255 W0, 256-511 D, 512-767 R
__device__ float g_WtA[KD * NH];      // hidden conv A, pair-transposed
__device__ float g_WtB[KD * NH];      // hidden conv B, pair-transposed
__device__ float g_Wcat2[KD * NC];    // final conv plain [192,16]
__device__ int    g_off[N_NODES + 1];
__device__ int    g_deg[N_NODES];
__device__ int    g_cur[N_NODES];
__device__ float2 g_edge[N_EDGES];    // (src-as-float-bits, p)

// ---------------- packed f32x2 helpers --------------------------------------
typedef unsigned long long u64;
__device__ __forceinline__ void ffma2(u64& d, u64 a, u64 b) {
    asm("fma.rn.f32x2 %0, %1, %2, %0;" : "+l"(d) : "l"(a), "l"(b));
}
__device__ __forceinline__ u64 pack2_dup(float x) {
    u64 r;
    unsigned int u = __float_as_uint(x);
    asm("mov.b64 %0, {%1, %1};" : "=l"(r) : "r"(u));
    return r;
}
__device__ __forceinline__ void unpack2(u64 v, float& lo, float& hi) {
    unsigned int a, b;
    asm("mov.b64 {%0, %1}, %2;" : "=r"(a), "=r"(b) : "l"(v));
    lo = __uint_as_float(a);
    hi = __uint_as_float(b);
}

// ---------------- CSR build --------------------------------------------------
__global__ void k_zero() {
    int i = blockIdx.x * blockDim.x + threadIdx.x;
    if (i < N_NODES) { g_deg[i] = 0; g_cur[i] = 0; }
}
__global__ void k_hist(const int* __restrict__ dst) {
    int e = blockIdx.x * blockDim.x + threadIdx.x;
    if (e < N_EDGES) atomicAdd(&g_deg[dst[e]], 1);
}
__global__ void k_scan() {
    __shared__ int sm[1024];
    int t = threadIdx.x;
    const int CH = (N_NODES + 1023) / 1024;
    int base = t * CH;
    int s = 0;
    for (int j = 0; j < CH; j++) {
        int i = base + j;
        if (i < N_NODES) s += g_deg[i];
    }
    sm[t] = s;
    __syncthreads();
    for (int d = 1; d < 1024; d <<= 1) {
        int v = (t >= d) ? sm[t - d] : 0;
        __syncthreads();
        sm[t] += v;
        __syncthreads();
    }
    int run = sm[t] - s;
    for (int j = 0; j < CH; j++) {
        int i = base + j;
        if (i < N_NODES) { g_off[i] = run; run += g_deg[i]; }
    }
    if (t == 1023) g_off[N_NODES] = run;
}
__global__ void k_scatter(const int* __restrict__ src, const int* __restrict__ dst,
                          const float* __restrict__ p) {
    int e = blockIdx.x * blockDim.x + threadIdx.x;
    if (e >= N_EDGES) return;
    int d = dst[e];
    int pos = atomicAdd(&g_cur[d], 1);
    int idx = g_off[d] + pos;
    g_edge[idx] = make_float2(__int_as_float(src[e]), p[e]);
}

// ---------------- all weight prep in ONE kernel ------------------------------
__global__ void k_wprep(const float* __restrict__ W1, const float* __restrict__ R1w,
                        const float* __restrict__ Wa, const float* __restrict__ Ra,
                        const float* __restrict__ Wb, const float* __restrict__ Rb,
                        const float* __restrict__ W2, const float* __restrict__ R2w) {
    int i = blockIdx.x * blockDim.x + threadIdx.x;
    if (i < KD1 * NH) {
        int k = i >> 6, c = i & 63;
        float v;
        if (k < NF)            v = W1[k * 64 + c];
        else if (k < 2 * NF)   v = W1[(NF + (k - NF)) * 64 + c] - W1[(k - NF) * 64 + c];
        else                   v = R1w[(k - 2 * NF) * 64 + c];
        g_Wcat1[i] = v;
        return;
    }
    i -= KD1 * NH;
    if (i < 2 * KD * NH) {
        const float* W = (i < KD * NH) ? Wa : Wb;
        const float* R = (i < KD * NH) ? Ra : Rb;
        float* out     = (i < KD * NH) ? g_WtA : g_WtB;
        int t = i % (KD * NH);
        int k2 = t >> 7, rem = t & 127, c = rem >> 1, j = rem & 1;
        int kk = 2 * k2 + j;
        float v;
        if (kk < NH)           v = W[kk * 64 + c];
        else if (kk < 2 * NH)  v = W[(NH + (kk - NH)) * 64 + c] - W[(kk - NH) * 64 + c];
        else                   v = R[(kk - 2 * NH) * 64 + c];
        out[t] = v;
        return;
    }
    i -= 2 * KD * NH;
    if (i < KD * NC) {
        int k = i >> 4, c = i & 15;
        float v;
        if (k < NH)            v = W2[k * 16 + c];
        else if (k < 2 * NH)   v = W2[(NH + (k - NH)) * 16 + c] - W2[(k - NH) * 16 + c];
        else                   v = R2w[(k - 2 * NH) * 16 + c];
        g_Wcat2[i] = v;
    }
}

// ---------------- conv1 dense GEMM (packed f32x2), 3 col-segments ----------
__global__ void __launch_bounds__(256) k_gemm192(const float* __restrict__ X) {
    __shared__ __align__(16) float As[16][132];
    __shared__ __align__(16) float Bs[16][64];
    int tid  = threadIdx.x;
    int row0 = blockIdx.x * 128;
    int seg  = blockIdx.y;
    const float* Wseg = g_Wcat1 + seg * NF * 64;
    int tx = tid & 7, ty = tid >> 3;
    u64 acc[4][4];
#pragma unroll
    for (int i = 0; i < 4; i++)
#pragma unroll
        for (int j = 0; j < 4; j++) acc[i][j] = 0ULL;
    int c  = tid & 15;
    int rb = tid >> 4;
#pragma unroll 1
    for (int kk = 0; kk < NF; kk += 16) {
#pragma unroll
        for (int i = 0; i < 8; i++) {
            int r = i * 16 + rb;
            int grow = row0 + r;
            As[c][r] = (grow < N_NODES) ? X[grow * NF + kk + c] : 0.f;
        }
#pragma unroll
        for (int i = 0; i < 4; i++) {
            int idx = tid + i * 256;
            Bs[idx >> 6][idx & 63] = Wseg[(kk + (idx >> 6)) * 64 + (idx & 63)];
        }
        __syncthreads();
#pragma unroll
        for (int k = 0; k < 16; k++) {
            float4 aa = *(const float4*)&As[k][ty * 4];
            ulonglong2 w01 = *(const ulonglong2*)&Bs[k][tx * 8];
            ulonglong2 w23 = *(const ulonglong2*)&Bs[k][tx * 8 + 4];
            u64 ap[4] = {pack2_dup(aa.x), pack2_dup(aa.y),
                         pack2_dup(aa.z), pack2_dup(aa.w)};
            u64 bp[4] = {w01.x, w01.y, w23.x, w23.y};
#pragma unroll
            for (int i = 0; i < 4; i++)
#pragma unroll
                for (int j = 0; j < 4; j++) ffma2(acc[i][j], ap[i], bp[j]);
        }
        __syncthreads();
    }
#pragma unroll
    for (int i = 0; i < 4; i++) {
        int grow = row0 + ty * 4 + i;
        if (grow < N_NODES) {
#pragma unroll
            for (int j = 0; j < 4; j++) {
                int c0 = tx * 4 + j;
                float lo, hi;
                unpack2(acc[i][j], lo, hi);
                if (seg < 2)
                    *(float2*)&g_XG[grow * 128 + 4 * c0 + 2 * seg] = make_float2(lo, hi);
                else
                    *(float2*)&g_XR[grow * 64 + 2 * c0] = make_float2(lo, hi);
            }
        }
    }
}

// ---------------- conv1 gather on [xW0|xD] pairs + bias + tanh -> h ---------
__global__ void __launch_bounds__(256) k_cagg1(const float* __restrict__ b1,
                                               float* __restrict__ H) {
    __shared__ float2 Stg[8][32];
    int wid = threadIdx.x >> 5, lane = threadIdx.x & 31;
    int node = blockIdx.x * 8 + wid;
    if (node >= N_NODES) return;
    int s0 = g_off[node], s1 = g_off[node + 1];
    const float4* G4 = (const float4*)g_XG;
    float2* stg = Stg[wid];
    float u0x = 0.f, u0y = 0.f, u1x = 0.f, u1y = 0.f;
    for (int e0 = s0; e0 < s1; e0 += 32) {
        int e = e0 + lane;
        if (e < s1) stg[lane] = g_edge[e];
        __syncwarp();
        int cnt = min(32, s1 - e0);
        int j = 0;
        for (; j + 4 <= cnt; j += 4) {
            float2 eA = stg[j], eB = stg[j + 1], eC = stg[j + 2], eD = stg[j + 3];
            float4 vA = G4[__float_as_int(eA.x) * 32 + lane];
            float4 vB = G4[__float_as_int(eB.x) * 32 + lane];
            float4 vC = G4[__float_as_int(eC.x) * 32 + lane];
            float4 vD = G4[__float_as_int(eD.x) * 32 + lane];
            u0x += (vA.x + vB.x) + (vC.x + vD.x);
            u0y += (vA.y + vB.y) + (vC.y + vD.y);
            u1x += eA.y * vA.z + eB.y * vB.z + eC.y * vC.z + eD.y * vD.z;
            u1y += eA.y * vA.w + eB.y * vB.w + eC.y * vC.w + eD.y * vD.w;
        }
        for (; j < cnt; j++) {
            float2 ev = stg[j];
            float4 v = G4[__float_as_int(ev.x) * 32 + lane];
            u0x += v.x; u0y += v.y;
            u1x += ev.y * v.z; u1y += ev.y * v.w;
        }
        __syncwarp();
    }
    float inv = 1.0f / (float)max(s1 - s0, 1);
    float2 xr = ((const float2*)g_XR)[node * 32 + lane];
    float vA = (u0x + u1x) * inv + xr.x + b1[2 * lane];
    float vB = (u0y + u1y) * inv + xr.y + b1[2 * lane + 1];
    ((float2*)H)[node * 32 + lane] = make_float2(tanhf(vA), tanhf(vB));
}

// ---- v2 staged gather: lanes 0-15 even edges / 16-31 odd edges, float4 -----
// lane owns channels 4*cg..4*cg+3 (cg = lane&15). Result reduced across parity.
__device__ __forceinline__ void gather_node4(
        const float4* __restrict__ X4, float2* __restrict__ stg,
        int lane, int ep, int cg, int s0, int s1,
        float4& u0, float4& u1) {
    u0 = make_float4(0.f, 0.f, 0.f, 0.f);
    u1 = make_float4(0.f, 0.f, 0.f, 0.f);
    for (int e0 = s0; e0 < s1; e0 += 32) {
        int e = e0 + lane;
        if (e < s1) stg[lane] = g_edge[e];
        __syncwarp();
        int cnt = min(32, s1 - e0);
        int j = 0;
        for (; j + 8 <= cnt; j += 8) {
            float2 eA = stg[j + ep];
            float2 eB = stg[j + 2 + ep];
            float2 eC = stg[j + 4 + ep];
            float2 eD = stg[j + 6 + ep];
            float4 vA = X4[__float_as_int(eA.x) * 16 + cg];
            float4 vB = X4[__float_as_int(eB.x) * 16 + cg];
            float4 vC = X4[__float_as_int(eC.x) * 16 + cg];
            float4 vD = X4[__float_as_int(eD.x) * 16 + cg];
            u0.x += (vA.x + vB.x) + (vC.x + vD.x);
            u0.y += (vA.y + vB.y) + (vC.y + vD.y);
            u0.z += (vA.z + vB.z) + (vC.z + vD.z);
            u0.w += (vA.w + vB.w) + (vC.w + vD.w);
            u1.x += eA.y * vA.x + eB.y * vB.x + eC.y * vC.x + eD.y * vD.x;
            u1.y += eA.y * vA.y + eB.y * vB.y + eC.y * vC.y + eD.y * vD.y;
            u1.z += eA.y * vA.z + eB.y * vB.z + eC.y * vC.z + eD.y * vD.z;
            u1.w += eA.y * vA.w + eB.y * vB.w + eC.y * vC.w + eD.y * vD.w;
        }
        for (; j < cnt; j += 2) {
            if (j + ep < cnt) {
                float2 ev = stg[j + ep];
                float4 v = X4[__float_as_int(ev.x) * 16 + cg];
                u0.x += v.x; u0.y += v.y; u0.z += v.z; u0.w += v.w;
                u1.x += ev.y * v.x; u1.y += ev.y * v.y;
                u1.z += ev.y * v.z; u1.w += ev.y * v.w;
            }
        }
        __syncwarp();
    }
    u0.x += __shfl_xor_sync(0xffffffffu, u0.x, 16);
    u0.y += __shfl_xor_sync(0xffffffffu, u0.y, 16);
    u0.z += __shfl_xor_sync(0xffffffffu, u0.z, 16);
    u0.w += __shfl_xor_sync(0xffffffffu, u0.w, 16);
    u1.x += __shfl_xor_sync(0xffffffffu, u1.x, 16);
    u1.y += __shfl_xor_sync(0xffffffffu, u1.y, 16);
    u1.z += __shfl_xor_sync(0xffffffffu, u1.z, 16);
    u1.w += __shfl_xor_sync(0xffffffffu, u1.w, 16);
}

// ---------------- FUSED hidden conv: 4-node batches, 3 CTAs/SM --------------
// MODE 0: Yout = conv(Xin)
// MODE 1: Yout = conv(Xin);  Yaux = H + cmul * Yout
// MODE 2: Yaux = H + 0.5*(k1 + 2 k2 + 2 k3 + conv(Xin))
template <int MODE>
__global__ void __launch_bounds__(256, 3) k_conv64f(
        const float* __restrict__ Xin, const float* __restrict__ Wt,
        const float* __restrict__ bias,
        float* __restrict__ Yout, float* __restrict__ Yaux,
        const float* __restrict__ H, float cmul) {
    extern __shared__ float sm[];
    float* Ws = sm;                                       // 12288 floats
    float* Sa = sm + KD * 64;                             // 8 warps * 4 nodes * KD = 6144
    float2* stgAll = (float2*)(sm + KD * 64 + 8 * 4 * KD); // 8 warps * 32 float2
    for (int i = threadIdx.x; i < KD * 64; i += 256) Ws[i] = Wt[i];
    __syncthreads();

    int wid = threadIdx.x >> 5, lane = threadIdx.x & 31;
    int ep = lane >> 4, cg = lane & 15;
    float* myA  = Sa + wid * (4 * KD);
    float2* stg = stgAll + wid * 32;
    const float4* X4 = (const float4*)Xin;
    float bs0 = bias[2 * lane], bs1 = bias[2 * lane + 1];

    int gw0    = (blockIdx.x * 8 + wid) * 4;
    int stride = gridDim.x * 32;
    for (int base = gw0; base < N_NODES; base += stride) {
        int nn = min(4, N_NODES - base);
        // prefetch own rows (independent loads; lanes 16-31 dedup with 0-15)
        float4 xv[4];
#pragma unroll
        for (int n = 0; n < 4; n++)
            if (n < nn) xv[n] = X4[(base + n) * 16 + cg];
        // ---- gather phase ----
        for (int n = 0; n < nn; n++) {
            int node = base + n;
            int s0 = g_off[node], s1 = g_off[node + 1];
            float4 u0, u1;
            gather_node4(X4, stg, lane, ep, cg, s0, s1, u0, u1);
            float inv = 1.0f / (float)max(s1 - s0, 1);
            if (lane < 16) {
                float* an = myA + n * KD;
                *(float4*)&an[4 * cg] =
                    make_float4(u0.x * inv, u0.y * inv, u0.z * inv, u0.w * inv);
                *(float4*)&an[64 + 4 * cg] =
                    make_float4(u1.x * inv, u1.y * inv, u1.z * inv, u1.w * inv);
                *(float4*)&an[128 + 4 * cg] = xv[n];
            }
        }
        __syncwarp();
        // ---- FMA phase: lane owns cols {2l, 2l+1}; packed over k-pairs ----
        u64 accA[4], accB[4];
#pragma unroll
        for (int n = 0; n < 4; n++) { accA[n] = 0ULL; accB[n] = 0ULL; }
#pragma unroll 4
        for (int k2 = 0; k2 < KD / 2; k2 += 2) {
            ulonglong2 w0 = *(const ulonglong2*)&Ws[k2 * 128 + lane * 4];
            ulonglong2 w1 = *(const ulonglong2*)&Ws[(k2 + 1) * 128 + lane * 4];
#pragma unroll
            for (int n = 0; n < 4; n++) {
                ulonglong2 av = *(const ulonglong2*)&myA[n * KD + 2 * k2];
                ffma2(accA[n], av.x, w0.x);
                ffma2(accB[n], av.x, w0.y);
                ffma2(accA[n], av.y, w1.x);
                ffma2(accB[n], av.y, w1.y);
            }
        }
        // ---- epilogue ----
        for (int n = 0; n < nn; n++) {
            int node = base + n;
            float aLo, aHi, bLo, bHi;
            unpack2(accA[n], aLo, aHi);
            unpack2(accB[n], bLo, bHi);
            float vA = aLo + aHi + bs0;
            float vB = bLo + bHi + bs1;
            if (MODE == 0) {
                ((float2*)Yout)[node * 32 + lane] = make_float2(vA, vB);
            } else if (MODE == 1) {
                ((float2*)Yout)[node * 32 + lane] = make_float2(vA, vB);
                float2 h2 = ((const float2*)H)[node * 32 + lane];
                ((float2*)Yaux)[node * 32 + lane] =
                    make_float2(h2.x + cmul * vA, h2.y + cmul * vB);
            } else {
                float2 h2 = ((const float2*)H)[node * 32 + lane];
                float2 a1 = ((const float2*)g_k1)[node * 32 + lane];
                float2 a2 = ((const float2*)g_k2)[node * 32 + lane];
                float2 a3 = ((const float2*)g_k3)[node * 32 + lane];
                ((float2*)Yaux)[node * 32 + lane] = make_float2(
                    h2.x + 0.5f * (a1.x + 2.f * a2.x + 2.f * a3.x + vA),
                    h2.y + 0.5f * (a1.y + 2.f * a2.y + 2.f * a3.y + vB));
            }
        }
        __syncwarp();
    }
}

// ---------------- FUSED final conv + tanh + log_softmax ---------------------
__global__ void __launch_bounds__(256) k_conv16f(
        const float* __restrict__ Yin, const float* __restrict__ b2,
        float* __restrict__ out) {
    __shared__ float  Ws[KD * NC];
    __shared__ __align__(16) float Sa[8][KD];
    __shared__ float2 Stg[8][32];
    for (int i = threadIdx.x; i < KD * NC; i += 256) Ws[i] = g_Wcat2[i];
    __syncthreads();
    int wid = threadIdx.x >> 5, lane = threadIdx.x & 31;
    int ep = lane >> 4, cg = lane & 15;
    int node = blockIdx.x * 8 + wid;
    if (node >= N_NODES) return;
    const float4* X4 = (const float4*)Yin;
    int s0 = g_off[node], s1 = g_off[node + 1];
    float4 u0, u1;
    gather_node4(X4, Stg[wid], lane, ep, cg, s0, s1, u0, u1);
    float inv = 1.0f / (float)max(s1 - s0, 1);
    float4 xv = X4[node * 16 + cg];
    if (lane < 16) {
        *(float4*)&Sa[wid][4 * cg] =
            make_float4(u0.x * inv, u0.y * inv, u0.z * inv, u0.w * inv);
        *(float4*)&Sa[wid][64 + 4 * cg] =
            make_float4(u1.x * inv, u1.y * inv, u1.z * inv, u1.w * inv);
        *(float4*)&Sa[wid][128 + 4 * cg] = xv;
    }
    __syncwarp();
    int half = lane >> 4, c = lane & 15;
    const float* a = &Sa[wid][96 * half];
    const float* w = &Ws[(96 * half) * 16 + c];
    float acc = 0.f;
#pragma unroll 4
    for (int k = 0; k < 96; k++) acc += a[k] * w[k * 16];
    acc += __shfl_down_sync(0xffffffffu, acc, 16);
    float v = tanhf(acc + b2[c]);
    float m = v;
#pragma unroll
    for (int off = 8; off; off >>= 1) m = fmaxf(m, __shfl_xor_sync(0xffffffffu, m, off));
    float s = expf(v - m);
#pragma unroll
    for (int off = 8; off; off >>= 1) s += __shfl_xor_sync(0xffffffffu, s, off);
    float lse = m + logf(s);
    if (lane < 16) out[node * 16 + c] = v - lse;
}

// ---------------- driver -----------------------------------------------------
extern "C" void kernel_launch(void* const* d_in, const int* in_sizes, int n_in,
                              void* d_out, int out_size) {
    const float* x   = (const float*)d_in[0];
    const float* p   = (const float*)d_in[1];
    const int*   src = (const int*)  d_in[2];
    const int*   dst = (const int*)  d_in[3];
    const float* W1  = (const float*)d_in[4];
    const float* R1  = (const float*)d_in[5];
    const float* b1  = (const float*)d_in[6];
    const float* Wa  = (const float*)d_in[7];
    const float* Ra  = (const float*)d_in[8];
    const float* ba  = (const float*)d_in[9];
    const float* Wb  = (const float*)d_in[10];
    const float* Rb  = (const float*)d_in[11];
    const float* bb  = (const float*)d_in[12];
    const float* W2  = (const float*)d_in[13];
    const float* R2  = (const float*)d_in[14];
    const float* b2  = (const float*)d_in[15];
    float* out = (float*)d_out;

    void* tmp;
    float *ph, *py, *pt, *pk1, *pk2, *pk3, *pWtA, *pWtB;
    cudaGetSymbolAddress(&tmp, g_h);   ph  = (float*)tmp;
    cudaGetSymbolAddress(&tmp, g_y);   py  = (float*)tmp;
    cudaGetSymbolAddress(&tmp, g_t);   pt  = (float*)tmp;
    cudaGetSymbolAddress(&tmp, g_k1);  pk1 = (float*)tmp;
    cudaGetSymbolAddress(&tmp, g_k2);  pk2 = (float*)tmp;
    cudaGetSymbolAddress(&tmp, g_k3);  pk3 = (float*)tmp;
    cudaGetSymbolAddress(&tmp, g_WtA); pWtA = (float*)tmp;
    cudaGetSymbolAddress(&tmp, g_WtB); pWtB = (float*)tmp;

    const int SMB = (KD * 64 + 8 * 4 * KD + 8 * 32 * 2) * 4;   // 75776 bytes
    cudaFuncSetAttribute(k_conv64f<0>, cudaFuncAttributeMaxDynamicSharedMemorySize, SMB);
    cudaFuncSetAttribute(k_conv64f<1>, cudaFuncAttributeMaxDynamicSharedMemorySize, SMB);
    cudaFuncSetAttribute(k_conv64f<2>, cudaFuncAttributeMaxDynamicSharedMemorySize, SMB);

    const int EB = (N_EDGES + 255) / 256;
    const int NB = (N_NODES + 255) / 256;
    const int WB = (N_NODES + 7) / 8;   // block per 8 nodes (warp per node)
    const int CG = 444;                 // persistent, 3 blocks/SM

    // CSR build
    k_zero<<<NB, 256>>>();
    k_hist<<<EB, 256>>>(dst);
    k_scan<<<1, 1024>>>();
    k_scatter<<<EB, 256>>>(src, dst, p);

    // all weight prep (one launch)
    k_wprep<<<(KD1 * NH + 2 * KD * NH + KD * NC + 255) / 256, 256>>>(
        W1, R1, Wa, Ra, Wb, Rb, W2, R2);

    // conv1 GEMM-first: XG = x@[W0|D] (interleaved), XR = x@R ; then gather
    {
        dim3 g((N_NODES + 127) / 128, 3);
        k_gemm192<<<g, 256>>>(x);
    }
    k_cagg1<<<WB, 256>>>(b1, ph);

    // RK4 (T=3): k_i from fused double-conv, axpy folded into epilogues
    k_conv64f<0><<<CG, 256, SMB>>>(ph, pWtA, ba, pt, nullptr, nullptr, 0.f);
    k_conv64f<1><<<CG, 256, SMB>>>(pt, pWtB, bb, pk1, py, ph, 1.5f);
    k_conv64f<0><<<CG, 256, SMB>>>(py, pWtA, ba, pt, nullptr, nullptr, 0.f);
    k_conv64f<1><<<CG, 256, SMB>>>(pt, pWtB, bb, pk2, py, ph, 1.5f);
    k_conv64f<0><<<CG, 256, SMB>>>(py, pWtA, ba, pt, nullptr, nullptr, 0.f);
    k_conv64f<1><<<CG, 256, SMB>>>(pt, pWtB, bb, pk3, py, ph, 3.0f);
    k_conv64f<0><<<CG, 256, SMB>>>(py, pWtA, ba, pt, nullptr, nullptr, 0.f);
    k_conv64f<2><<<CG, 256, SMB>>>(pt, pWtB, bb, pt, py, ph, 0.f);

    // conv2 + tanh + log_softmax -> out
    k_conv16f<<<WB, 256>>>(py, b2, out);
}